// round 1
// baseline (speedup 1.0000x reference)
#include <cuda_runtime.h>
#include <cstdint>

#define NN 116736   // nodes = 2048*57
#define NE 327680   // edges = 2048*160
#define MF 163840   // branch edges = 2048*80
#define NL 5
#define HID 256

// ---------------- scratch (device globals; no allocations allowed) ----------
static __device__ float g_h0[(size_t)NN * HID];
static __device__ float g_h1[(size_t)NN * HID];
static __device__ float g_b [(size_t)NN * HID];
static __device__ float g_c [(size_t)NN * HID];
static __device__ float g_a [(size_t)MF * HID];   // big buffer (also holds final hidden)
static __device__ int   g_cnt[NN];
static __device__ float g_deginv[NN];
static __device__ float g_gate[NN];
static __device__ float g_bns[NL * HID];
static __device__ float g_bnt[NL * HID];
static __device__ int   g_uidx[MF];
static __device__ int   g_vidx[MF];

// ---------------- helpers ---------------------------------------------------
__device__ __forceinline__ float2 u64_as_f2(unsigned long long v) {
    float2 r;
    asm("mov.b64 {%0, %1}, %2;" : "=f"(r.x), "=f"(r.y) : "l"(v));
    return r;
}

// ---------------- generic K=256, N=256 GEMM (FFMA2 core) --------------------
// C[M,256] = A1@B1 (+ A2@B2) (+ bias*gate), optional per-row scale on A1,
// optional row-gather indices, epilogue: 0=none, 1=relu, 2=BN+relu+residual.
__global__ __launch_bounds__(256) void gemm256_kernel(
    const float* __restrict__ A1, const float* __restrict__ B1,
    const float* __restrict__ A2, const float* __restrict__ B2,
    const float* __restrict__ bias,
    const float* __restrict__ rowscale,
    const float* __restrict__ biasgate,
    const int*   __restrict__ idx1, const int* __restrict__ idx2,
    const float* __restrict__ resid,
    const float* __restrict__ bn_s, const float* __restrict__ bn_t,
    float* __restrict__ C, int M, int epilogue)
{
    __shared__ float As[16][128];
    __shared__ float Bs[16][128];
    const int tid  = threadIdx.x;
    const int row0 = blockIdx.y * 128;
    const int col0 = blockIdx.x * 128;
    const int tm   = (tid >> 4) * 8;
    const int tn   = (tid & 15) * 8;

    unsigned long long acc[8][4];
    #pragma unroll
    for (int i = 0; i < 8; i++)
        #pragma unroll
        for (int j = 0; j < 4; j++) acc[i][j] = 0ull;

    const int nphase = (A2 != nullptr) ? 2 : 1;
    for (int phase = 0; phase < nphase; ++phase) {
        const float* A   = phase ? A2 : A1;
        const float* B   = phase ? B2 : B1;
        const int*   idx = phase ? idx2 : idx1;
        const bool dosc  = (phase == 0) && (rowscale != nullptr);

        for (int kt = 0; kt < 256; kt += 16) {
            float4 av[2], bv[2];
            #pragma unroll
            for (int i = 0; i < 2; i++) {
                int f = tid + i * 256;
                int r = f >> 2;
                int kc = (f & 3) << 2;
                int grow = row0 + r;
                int arow = idx ? idx[grow] : grow;
                av[i] = *(const float4*)&A[(size_t)arow * 256 + kt + kc];
                if (dosc) {
                    float s = rowscale[arow];
                    av[i].x *= s; av[i].y *= s; av[i].z *= s; av[i].w *= s;
                }
            }
            #pragma unroll
            for (int i = 0; i < 2; i++) {
                int f = tid + i * 256;
                int r = f >> 5;
                int nc = (f & 31) << 2;
                bv[i] = *(const float4*)&B[(size_t)(kt + r) * 256 + col0 + nc];
            }
            __syncthreads();
            #pragma unroll
            for (int i = 0; i < 2; i++) {
                int f = tid + i * 256;
                int r = f >> 2;
                int kc = (f & 3) << 2;
                As[kc + 0][r] = av[i].x; As[kc + 1][r] = av[i].y;
                As[kc + 2][r] = av[i].z; As[kc + 3][r] = av[i].w;
                int rb = f >> 5;
                int nc = (f & 31) << 2;
                *(float4*)&Bs[rb][nc] = bv[i];
            }
            __syncthreads();
            #pragma unroll
            for (int k = 0; k < 16; k++) {
                float4 a0 = *(const float4*)&As[k][tm];
                float4 a1 = *(const float4*)&As[k][tm + 4];
                ulonglong2 b0 = *(const ulonglong2*)&Bs[k][tn];
                ulonglong2 b1 = *(const ulonglong2*)&Bs[k][tn + 4];
                float ar[8] = {a0.x, a0.y, a0.z, a0.w, a1.x, a1.y, a1.z, a1.w};
                unsigned long long bb[4] = {b0.x, b0.y, b1.x, b1.y};
                #pragma unroll
                for (int i = 0; i < 8; i++) {
                    unsigned long long ad;
                    asm("mov.b64 %0, {%1, %1};" : "=l"(ad) : "f"(ar[i]));
                    #pragma unroll
                    for (int j = 0; j < 4; j++)
                        asm("fma.rn.f32x2 %0, %1, %2, %0;"
                            : "+l"(acc[i][j]) : "l"(ad), "l"(bb[j]));
                }
            }
        }
    }

    // epilogue
    #pragma unroll
    for (int i = 0; i < 8; i++) {
        int r = row0 + tm + i;
        float gate = biasgate ? biasgate[r] : 1.0f;
        #pragma unroll
        for (int j2 = 0; j2 < 4; j2++) {
            float2 p = u64_as_f2(acc[i][j2]);
            int c0 = col0 + tn + j2 * 2;
            float vx = p.x, vy = p.y;
            if (bias) { vx += bias[c0] * gate; vy += bias[c0 + 1] * gate; }
            if (epilogue == 1) {
                vx = fmaxf(vx, 0.f); vy = fmaxf(vy, 0.f);
            } else if (epilogue == 2) {
                vx = fmaxf(vx * bn_s[c0]     + bn_t[c0],     0.f) + resid[(size_t)r * 256 + c0];
                vy = fmaxf(vy * bn_s[c0 + 1] + bn_t[c0 + 1], 0.f) + resid[(size_t)r * 256 + c0 + 1];
            }
            C[(size_t)r * 256 + c0]     = vx;
            C[(size_t)r * 256 + c0 + 1] = vy;
        }
    }
}

// ---------------- input GEMM: h = x[N,16] @ in_w[16,256] + in_b -------------
__global__ __launch_bounds__(256) void ingemm_kernel(
    const float* __restrict__ x, const float* __restrict__ w,
    const float* __restrict__ bias, float* __restrict__ h)
{
    __shared__ float ws[16][256];
    __shared__ float xs[32][16];
    int c = threadIdx.x;
    #pragma unroll
    for (int k = 0; k < 16; k++) ws[k][c] = w[k * 256 + c];
    int r0 = blockIdx.x * 32;
    for (int i = threadIdx.x; i < 512; i += 256) xs[i >> 4][i & 15] = x[(size_t)r0 * 16 + i];
    __syncthreads();
    float bb = bias[c];
    for (int r = 0; r < 32; r++) {
        float acc = bb;
        #pragma unroll
        for (int k = 0; k < 16; k++) acc += xs[r][k] * ws[k][c];
        h[(size_t)(r0 + r) * 256 + c] = acc;
    }
}

// ---------------- degree / BN / index precompute ----------------------------
__global__ void count_kernel(const int* __restrict__ ei, int* __restrict__ cnt) {
    int e = blockIdx.x * 256 + threadIdx.x;
    if (e < NE) atomicAdd(&cnt[ei[NE + e]], 1);
}

__global__ void deg_kernel(const int* __restrict__ cnt, float* __restrict__ deginv,
                           float* __restrict__ gate) {
    int n = blockIdx.x * 256 + threadIdx.x;
    if (n < NN) {
        int c = cnt[n];
        deginv[n] = 1.0f / (float)max(c, 1);
        gate[n]   = (c > 0) ? 1.0f : 0.0f;
    }
}

__global__ void bnprep_kernel(const float* __restrict__ g, const float* __restrict__ b,
                              const float* __restrict__ m, const float* __restrict__ v,
                              float* __restrict__ s, float* __restrict__ t) {
    int i = blockIdx.x * 256 + threadIdx.x;
    if (i < NL * HID) {
        float sc = g[i] * rsqrtf(v[i] + 1e-5f);
        s[i] = sc;
        t[i] = b[i] - m[i] * sc;
    }
}

__global__ void idx_kernel(int* __restrict__ u, int* __restrict__ v) {
    int r = blockIdx.x * 256 + threadIdx.x;
    if (r < MF) {
        int g = r / 80, i = r % 80;
        u[r] = g * 57 + (i % 57);
        v[r] = g * 57 + ((i * 13 + 1) % 57);
    }
}

// ---------------- edge phase: scatter relu(a[dst]+b[src]) into aggH ---------
__global__ __launch_bounds__(256) void edge_kernel(
    const float* __restrict__ a, const float* __restrict__ b,
    const int* __restrict__ ei, float* __restrict__ agg)
{
    int e = blockIdx.x * 8 + (threadIdx.x >> 5);
    int lane = threadIdx.x & 31;
    int s = ei[e];
    int d = ei[NE + e];
    size_t od = (size_t)d * 256 + lane * 8;
    size_t os = (size_t)s * 256 + lane * 8;
    float4 u0 = *(const float4*)(a + od);
    float4 u1 = *(const float4*)(a + od + 4);
    float4 v0 = *(const float4*)(b + os);
    float4 v1 = *(const float4*)(b + os + 4);
    float hv[8] = { fmaxf(u0.x + v0.x, 0.f), fmaxf(u0.y + v0.y, 0.f),
                    fmaxf(u0.z + v0.z, 0.f), fmaxf(u0.w + v0.w, 0.f),
                    fmaxf(u1.x + v1.x, 0.f), fmaxf(u1.y + v1.y, 0.f),
                    fmaxf(u1.z + v1.z, 0.f), fmaxf(u1.w + v1.w, 0.f) };
    #pragma unroll
    for (int i = 0; i < 8; i++) atomicAdd(&agg[od + i], hv[i]);
}

// ---------------- final dot: out = hidden_f @ mlp_w2 + mlp_b2 ---------------
__global__ __launch_bounds__(256) void outdot_kernel(
    const float* __restrict__ hf, const float* __restrict__ w2,
    const float* __restrict__ b2, float* __restrict__ out)
{
    int m = blockIdx.x * 8 + (threadIdx.x >> 5);
    int lane = threadIdx.x & 31;
    const float4* hp = (const float4*)(hf + (size_t)m * 256);
    const float4* wp = (const float4*)w2;
    float acc = 0.f;
    #pragma unroll
    for (int i = 0; i < 2; i++) {
        float4 h4 = hp[lane * 2 + i];
        float4 w4 = wp[lane * 2 + i];
        acc += h4.x * w4.x + h4.y * w4.y + h4.z * w4.z + h4.w * w4.w;
    }
    #pragma unroll
    for (int o = 16; o; o >>= 1) acc += __shfl_xor_sync(0xffffffffu, acc, o);
    if (lane == 0) out[m] = acc + b2[0];
}

// ---------------- launcher --------------------------------------------------
extern "C" void kernel_launch(void* const* d_in, const int* in_sizes, int n_in,
                              void* d_out, int out_size)
{
    const float* x      = (const float*)d_in[0];
    const int*   ei     = (const int*)  d_in[1];
    // d_in[2] = num_graphs (fixed 2048, baked into constants)
    const float* in_w   = (const float*)d_in[3];
    const float* in_b   = (const float*)d_in[4];
    const float* msg_w1 = (const float*)d_in[5];
    const float* msg_b1 = (const float*)d_in[6];
    const float* msg_w2 = (const float*)d_in[7];
    const float* msg_b2 = (const float*)d_in[8];
    const float* upd_w1 = (const float*)d_in[9];
    const float* upd_b1 = (const float*)d_in[10];
    const float* upd_w2 = (const float*)d_in[11];
    const float* upd_b2 = (const float*)d_in[12];
    const float* bn_g   = (const float*)d_in[13];
    const float* bn_b   = (const float*)d_in[14];
    const float* bn_m   = (const float*)d_in[15];
    const float* bn_v   = (const float*)d_in[16];
    const float* mlp_w1 = (const float*)d_in[17];
    const float* mlp_b1 = (const float*)d_in[18];
    const float* mlp_w2 = (const float*)d_in[19];
    const float* mlp_b2 = (const float*)d_in[20];
    float* out = (float*)d_out;

    float *h0, *h1, *ba, *bb, *bc, *deginv, *gate, *bns, *bnt;
    int *cnt, *uix, *vix;
    cudaGetSymbolAddress((void**)&h0, g_h0);
    cudaGetSymbolAddress((void**)&h1, g_h1);
    cudaGetSymbolAddress((void**)&bb, g_b);
    cudaGetSymbolAddress((void**)&bc, g_c);
    cudaGetSymbolAddress((void**)&ba, g_a);
    cudaGetSymbolAddress((void**)&cnt, g_cnt);
    cudaGetSymbolAddress((void**)&deginv, g_deginv);
    cudaGetSymbolAddress((void**)&gate, g_gate);
    cudaGetSymbolAddress((void**)&bns, g_bns);
    cudaGetSymbolAddress((void**)&bnt, g_bnt);
    cudaGetSymbolAddress((void**)&uix, g_uidx);
    cudaGetSymbolAddress((void**)&vix, g_vidx);

    cudaMemsetAsync(cnt, 0, NN * sizeof(int), 0);
    count_kernel<<<NE / 256, 256>>>(ei, cnt);
    deg_kernel<<<NN / 256, 256>>>(cnt, deginv, gate);
    bnprep_kernel<<<NL, 256>>>(bn_g, bn_b, bn_m, bn_v, bns, bnt);
    idx_kernel<<<MF / 256, 256>>>(uix, vix);
    ingemm_kernel<<<NN / 32, 256>>>(x, in_w, in_b, h0);

    dim3 gN(2, NN / 128);
    for (int l = 0; l < NL; l++) {
        float* hc = (l & 1) ? h1 : h0;
        float* hn = (l & 1) ? h0 : h1;
        const float* mw1 = msg_w1 + (size_t)l * 512 * 256;
        const float* mw2 = msg_w2 + (size_t)l * 256 * 256;
        const float* uw1 = upd_w1 + (size_t)l * 512 * 256;
        const float* uw2 = upd_w2 + (size_t)l * 256 * 256;

        // a = h @ w1_dst + msg_b1   (bias folded into dst half)
        gemm256_kernel<<<gN, 256>>>(hc, mw1, nullptr, nullptr, msg_b1 + l * 256,
                                    nullptr, nullptr, nullptr, nullptr,
                                    nullptr, nullptr, nullptr, ba, NN, 0);
        // b = h @ w1_src
        gemm256_kernel<<<gN, 256>>>(hc, mw1 + 256 * 256, nullptr, nullptr, nullptr,
                                    nullptr, nullptr, nullptr, nullptr,
                                    nullptr, nullptr, nullptr, bb, NN, 0);
        // aggH = scatter_add relu(a[dst] + b[src])
        cudaMemsetAsync(bc, 0, (size_t)NN * 256 * sizeof(float), 0);
        edge_kernel<<<NE / 8, 256>>>(ba, bb, ei, bc);
        // aggm = (aggH/deg) @ w2 + gate*b2
        gemm256_kernel<<<gN, 256>>>(bc, mw2, nullptr, nullptr, msg_b2 + l * 256,
                                    deginv, gate, nullptr, nullptr,
                                    nullptr, nullptr, nullptr, bb, NN, 0);
        // t = relu(h @ uw1_top + aggm @ uw1_bot + upd_b1)
        gemm256_kernel<<<gN, 256>>>(hc, uw1, bb, uw1 + 256 * 256, upd_b1 + l * 256,
                                    nullptr, nullptr, nullptr, nullptr,
                                    nullptr, nullptr, nullptr, ba, NN, 1);
        // h' = relu(BN(t @ uw2 + upd_b2)) + h
        gemm256_kernel<<<gN, 256>>>(ba, uw2, nullptr, nullptr, upd_b2 + l * 256,
                                    nullptr, nullptr, nullptr, nullptr,
                                    hc, bns + l * 256, bnt + l * 256, hn, NN, 2);
    }

    float* hf = h1;  // after 5 layers h lives in g_h1
    dim3 gF(2, MF / 128);
    // hidden_f = relu(h[u] @ mw1_top + h[v] @ mw1_bot + mlp_b1)
    gemm256_kernel<<<gF, 256>>>(hf, mlp_w1, hf, mlp_w1 + 256 * 256, mlp_b1,
                                nullptr, nullptr, uix, vix,
                                nullptr, nullptr, nullptr, ba, MF, 1);
    outdot_kernel<<<MF / 8, 256>>>(ba, mlp_w2, mlp_b2, out);
}

// round 3
// speedup vs baseline: 2.0134x; 2.0134x over previous
#include <cuda_runtime.h>
#include <cuda_bf16.h>
#include <cstdint>

#define NN 116736   // nodes = 2048*57
#define NE 327680   // edges = 2048*160
#define MF 163840   // branch rows = 2048*80
#define NL 5
#define HID 256

// ---------------- scratch (device globals; no allocations allowed) ----------
static __device__ float g_h0[(size_t)NN * HID];
static __device__ float g_h1[(size_t)NN * HID];
static __device__ float g_b [(size_t)NN * HID];
static __device__ float g_c [(size_t)NN * HID];
static __device__ float g_a [(size_t)MF * HID];   // big buffer (also final hidden)
static __device__ int   g_cnt[NN];
static __device__ float g_deginv[NN];
static __device__ float g_gate[NN];
static __device__ float g_bns[NL * HID];
static __device__ float g_bnt[NL * HID];
static __device__ int   g_uidx[MF];
static __device__ int   g_vidx[MF];

// transposed + bf16-split weights: layout [n][K] per matrix, concatenated
#define WT_LSTRIDE 393216
#define WT_MSGD 0
#define WT_MSGS 65536
#define WT_MSG2 131072
#define WT_UPD1 196608
#define WT_UPD2 327680
#define WT_MLP1 1966080
#define WT_TOTAL 2097152
static __device__ __nv_bfloat16 g_wth[WT_TOTAL];
static __device__ __nv_bfloat16 g_wtl[WT_TOTAL];

// ---------------- PTX helpers ------------------------------------------------
__device__ __forceinline__ uint32_t smem_u32(const void* p) {
    uint32_t a;
    asm("{ .reg .u64 t; cvta.to.shared.u64 t, %1; cvt.u32.u64 %0, t; }" : "=r"(a) : "l"(p));
    return a;
}
__device__ __forceinline__ void ldm_x4(uint32_t& r0, uint32_t& r1, uint32_t& r2,
                                       uint32_t& r3, uint32_t addr) {
    asm volatile("ldmatrix.sync.aligned.m8n8.x4.shared.b16 {%0,%1,%2,%3}, [%4];"
                 : "=r"(r0), "=r"(r1), "=r"(r2), "=r"(r3) : "r"(addr));
}
__device__ __forceinline__ void mma_bf16(float* d, const uint32_t* a, const uint32_t* b) {
    asm volatile("mma.sync.aligned.m16n8k16.row.col.f32.bf16.bf16.f32 "
                 "{%0,%1,%2,%3}, {%4,%5,%6,%7}, {%8,%9}, {%0,%1,%2,%3};"
                 : "+f"(d[0]), "+f"(d[1]), "+f"(d[2]), "+f"(d[3])
                 : "r"(a[0]), "r"(a[1]), "r"(a[2]), "r"(a[3]), "r"(b[0]), "r"(b[1]));
}

// SMEM layout (dynamic): per buffer: AH 10240B, AL 10240B, BH 10240B, BL 10240B
// tiles are 128 rows x 32 cols bf16, row stride padded to 40 halfs (80 B)
#define ABUF 10240
#define BUFSTRIDE 40960
#define SMEM_BYTES 81920

// ---------------- HMMA GEMM: C[M,256] = A@Wt^T (bf16x3 split, fp32 acc) -----
// K = 256 (single A) or 512 (dual: chunks 0-7 from A1, 8-15 from A2).
// mode: 0 = +bias*gate, 1 = relu(+bias), 2 = BN+relu+residual(+bias)
__global__ __launch_bounds__(256) void gemm_hmma(
    const float* __restrict__ A1, const float* __restrict__ A2,
    const int* __restrict__ idx1, const int* __restrict__ idx2,
    const float* __restrict__ rowscale,
    const __nv_bfloat16* __restrict__ wh, const __nv_bfloat16* __restrict__ wl, int K,
    const float* __restrict__ bias, const float* __restrict__ biasgate,
    const float* __restrict__ resid,
    const float* __restrict__ bn_s, const float* __restrict__ bn_t,
    float* __restrict__ C, int mode)
{
    extern __shared__ char smem[];
    const uint32_t sb = smem_u32(smem);
    const int tid  = threadIdx.x;
    const int wid  = tid >> 5;
    const int lane = tid & 31;
    const int wm   = wid & 3;        // 4 warps along M: 32 rows each
    const int wn   = wid >> 2;       // 2 warps along N: 64 cols each
    const int row0 = blockIdx.y * 128;
    const int col0 = blockIdx.x * 128;
    const int nch  = K >> 5;

    float acc[2][8][4];
    #pragma unroll
    for (int mt = 0; mt < 2; mt++)
        #pragma unroll
        for (int nt = 0; nt < 8; nt++)
            #pragma unroll
            for (int j = 0; j < 4; j++) acc[mt][nt][j] = 0.f;

    // per-lane ldmatrix address offsets (bytes, within a tile buffer)
    const uint32_t aoff = ((wm * 32 + (lane & 7) + ((lane >> 3) & 1) * 8) * 40
                           + ((lane >> 4) & 1) * 8) * 2;
    const uint32_t boff = ((wn * 64 + (lane & 7) + ((lane >> 4) & 1) * 8) * 40
                           + ((lane >> 3) & 1) * 8) * 2;

    float4 av[4];
    uint4  bvh[2], bvl[2];

    // ---- staging loads for chunk c -----------------------------------------
    auto load_regs = [&](int c) {
        const int kb = c * 32;
        const float* A;
        const int* idx;
        int kloc;
        if (A2 != nullptr && c >= 8) { A = A2; idx = idx2; kloc = kb - 256; }
        else                         { A = A1; idx = idx1; kloc = kb; }
        #pragma unroll
        for (int i = 0; i < 4; i++) {
            int f = tid + i * 256;
            int r = f >> 3;
            int c4 = (f & 7) << 2;
            int grow = row0 + r;
            int arow = idx ? idx[grow] : grow;
            float4 v = *(const float4*)&A[(size_t)arow * 256 + kloc + c4];
            if (rowscale) { float s = rowscale[arow]; v.x *= s; v.y *= s; v.z *= s; v.w *= s; }
            av[i] = v;
        }
        #pragma unroll
        for (int i = 0; i < 2; i++) {
            int f = tid + i * 256;
            int n = f >> 2;
            int k8 = (f & 3) << 3;
            size_t s0 = (size_t)(col0 + n) * K + kb + k8;
            bvh[i] = *(const uint4*)&wh[s0];
            bvl[i] = *(const uint4*)&wl[s0];
        }
    };
    // ---- store staged regs into smem buffer --------------------------------
    auto store_smem = [&](int buf) {
        char* sm = smem + buf * BUFSTRIDE;
        #pragma unroll
        for (int i = 0; i < 4; i++) {
            int f = tid + i * 256;
            int r = f >> 3;
            int c4 = (f & 7) << 2;
            float vf[4] = {av[i].x, av[i].y, av[i].z, av[i].w};
            uint32_t hw[4], lw[4];
            #pragma unroll
            for (int j = 0; j < 4; j++) {
                __nv_bfloat16 hb = __float2bfloat16(vf[j]);
                __nv_bfloat16 lb = __float2bfloat16(vf[j] - __bfloat162float(hb));
                hw[j] = (uint32_t)__bfloat16_as_ushort(hb);
                lw[j] = (uint32_t)__bfloat16_as_ushort(lb);
            }
            uint32_t off = (r * 40 + c4) * 2;
            *(uint2*)(sm + off)        = make_uint2(hw[0] | (hw[1] << 16), hw[2] | (hw[3] << 16));
            *(uint2*)(sm + ABUF + off) = make_uint2(lw[0] | (lw[1] << 16), lw[2] | (lw[3] << 16));
        }
        #pragma unroll
        for (int i = 0; i < 2; i++) {
            int f = tid + i * 256;
            int n = f >> 2;
            int k8 = (f & 3) << 3;
            uint32_t off = (n * 40 + k8) * 2;
            *(uint4*)(sm + 2 * ABUF + off) = bvh[i];
            *(uint4*)(sm + 3 * ABUF + off) = bvl[i];
        }
    };
    // ---- compute one chunk from smem buffer --------------------------------
    auto compute = [&](int buf) {
        const uint32_t base = sb + buf * BUFSTRIDE;
        #pragma unroll
        for (int ks = 0; ks < 2; ks++) {
            uint32_t ah[2][4], al[2][4];
            #pragma unroll
            for (int mt = 0; mt < 2; mt++) {
                uint32_t ad = base + aoff + mt * 1280 + ks * 32;
                ldm_x4(ah[mt][0], ah[mt][1], ah[mt][2], ah[mt][3], ad);
                ldm_x4(al[mt][0], al[mt][1], al[mt][2], al[mt][3], ad + ABUF);
            }
            uint32_t bh[8][2], bl[8][2];
            #pragma unroll
            for (int p = 0; p < 4; p++) {
                uint32_t bd = base + 2 * ABUF + boff + p * 1280 + ks * 32;
                ldm_x4(bh[2 * p][0], bh[2 * p][1], bh[2 * p + 1][0], bh[2 * p + 1][1], bd);
                ldm_x4(bl[2 * p][0], bl[2 * p][1], bl[2 * p + 1][0], bl[2 * p + 1][1], bd + ABUF);
            }
            #pragma unroll
            for (int mt = 0; mt < 2; mt++)
                #pragma unroll
                for (int nt = 0; nt < 8; nt++) {
                    mma_bf16(acc[mt][nt], ah[mt], bh[nt]);
                    mma_bf16(acc[mt][nt], ah[mt], bl[nt]);
                    mma_bf16(acc[mt][nt], al[mt], bh[nt]);
                }
        }
    };

    // ---- double-buffered mainloop ------------------------------------------
    load_regs(0);
    store_smem(0);
    __syncthreads();
    for (int c = 0; c < nch; c++) {
        if (c + 1 < nch) load_regs(c + 1);
        compute(c & 1);
        __syncthreads();
        if (c + 1 < nch) {
            store_smem((c + 1) & 1);
            __syncthreads();
        }
    }

    // ---- epilogue straight from accumulator fragments ----------------------
    const int rw = row0 + wm * 32;
    const int cw = col0 + wn * 64;
    #pragma unroll
    for (int mt = 0; mt < 2; mt++) {
        #pragma unroll
        for (int hh = 0; hh < 2; hh++) {
            const int r = rw + mt * 16 + hh * 8 + (lane >> 2);
            const float gate = biasgate ? biasgate[r] : 1.0f;
            #pragma unroll
            for (int nt = 0; nt < 8; nt++) {
                const int cg = cw + nt * 8 + 2 * (lane & 3);
                float vx = acc[mt][nt][hh * 2 + 0];
                float vy = acc[mt][nt][hh * 2 + 1];
                if (bias) { vx += bias[cg] * gate; vy += bias[cg + 1] * gate; }
                if (mode == 1) {
                    vx = fmaxf(vx, 0.f); vy = fmaxf(vy, 0.f);
                } else if (mode == 2) {
                    const float2 rv = *(const float2*)&resid[(size_t)r * 256 + cg];
                    vx = fmaxf(vx * bn_s[cg]     + bn_t[cg],     0.f) + rv.x;
                    vy = fmaxf(vy * bn_s[cg + 1] + bn_t[cg + 1], 0.f) + rv.y;
                }
                *(float2*)&C[(size_t)r * 256 + cg] = make_float2(vx, vy);
            }
        }
    }
}

// ---------------- weight prep: transpose + bf16 hi/lo split -----------------
__global__ void wprep_kernel(const float* __restrict__ src, int sstride,
                             __nv_bfloat16* __restrict__ wh, __nv_bfloat16* __restrict__ wl,
                             int doff, int K)
{
    int l = blockIdx.y;
    int k = blockIdx.x;
    int n = threadIdx.x;
    float v = src[(size_t)l * sstride + (size_t)k * 256 + n];
    __nv_bfloat16 hb = __float2bfloat16(v);
    __nv_bfloat16 lb = __float2bfloat16(v - __bfloat162float(hb));
    size_t d = (size_t)doff + (size_t)l * WT_LSTRIDE + (size_t)n * K + k;
    wh[d] = hb;
    wl[d] = lb;
}

// ---------------- input GEMM: h = x[N,16] @ in_w[16,256] + in_b -------------
__global__ __launch_bounds__(256) void ingemm_kernel(
    const float* __restrict__ x, const float* __restrict__ w,
    const float* __restrict__ bias, float* __restrict__ h)
{
    __shared__ float ws[16][256];
    __shared__ float xs[32][16];
    int c = threadIdx.x;
    #pragma unroll
    for (int k = 0; k < 16; k++) ws[k][c] = w[k * 256 + c];
    int r0 = blockIdx.x * 32;
    for (int i = threadIdx.x; i < 512; i += 256) xs[i >> 4][i & 15] = x[(size_t)r0 * 16 + i];
    __syncthreads();
    float bb = bias[c];
    for (int r = 0; r < 32; r++) {
        float acc = bb;
        #pragma unroll
        for (int k = 0; k < 16; k++) acc += xs[r][k] * ws[k][c];
        h[(size_t)(r0 + r) * 256 + c] = acc;
    }
}

// ---------------- degree / BN / index precompute ----------------------------
__global__ void count_kernel(const int* __restrict__ ei, int* __restrict__ cnt) {
    int e = blockIdx.x * 256 + threadIdx.x;
    if (e < NE) atomicAdd(&cnt[ei[NE + e]], 1);
}
__global__ void deg_kernel(const int* __restrict__ cnt, float* __restrict__ deginv,
                           float* __restrict__ gate) {
    int n = blockIdx.x * 256 + threadIdx.x;
    if (n < NN) {
        int c = cnt[n];
        deginv[n] = 1.0f / (float)max(c, 1);
        gate[n]   = (c > 0) ? 1.0f : 0.0f;
    }
}
__global__ void bnprep_kernel(const float* __restrict__ g, const float* __restrict__ b,
                              const float* __restrict__ m, const float* __restrict__ v,
                              float* __restrict__ s, float* __restrict__ t) {
    int i = blockIdx.x * 256 + threadIdx.x;
    if (i < NL * HID) {
        float sc = g[i] * rsqrtf(v[i] + 1e-5f);
        s[i] = sc;
        t[i] = b[i] - m[i] * sc;
    }
}
__global__ void idx_kernel(int* __restrict__ u, int* __restrict__ v) {
    int r = blockIdx.x * 256 + threadIdx.x;
    if (r < MF) {
        int g = r / 80, i = r % 80;
        u[r] = g * 57 + (i % 57);
        v[r] = g * 57 + ((i * 13 + 1) % 57);
    }
}

// ---------------- edge phase: scatter relu(a[dst]+b[src]) into agg ----------
__global__ __launch_bounds__(256) void edge_kernel(
    const float* __restrict__ a, const float* __restrict__ b,
    const int* __restrict__ ei, float* __restrict__ agg)
{
    int e = blockIdx.x * 8 + (threadIdx.x >> 5);
    int lane = threadIdx.x & 31;
    int s = ei[e];
    int d = ei[NE + e];
    size_t od = (size_t)d * 256 + lane * 8;
    size_t os = (size_t)s * 256 + lane * 8;
    float4 u0 = *(const float4*)(a + od);
    float4 u1 = *(const float4*)(a + od + 4);
    float4 v0 = *(const float4*)(b + os);
    float4 v1 = *(const float4*)(b + os + 4);
    float h0x = fmaxf(u0.x + v0.x, 0.f), h0y = fmaxf(u0.y + v0.y, 0.f);
    float h0z = fmaxf(u0.z + v0.z, 0.f), h0w = fmaxf(u0.w + v0.w, 0.f);
    float h1x = fmaxf(u1.x + v1.x, 0.f), h1y = fmaxf(u1.y + v1.y, 0.f);
    float h1z = fmaxf(u1.z + v1.z, 0.f), h1w = fmaxf(u1.w + v1.w, 0.f);
    asm volatile("red.global.add.v4.f32 [%0], {%1, %2, %3, %4};"
                 :: "l"(agg + od), "f"(h0x), "f"(h0y), "f"(h0z), "f"(h0w) : "memory");
    asm volatile("red.global.add.v4.f32 [%0], {%1, %2, %3, %4};"
                 :: "l"(agg + od + 4), "f"(h1x), "f"(h1y), "f"(h1z), "f"(h1w) : "memory");
}

// ---------------- final dot: out = hidden_f @ mlp_w2 + mlp_b2 ---------------
__global__ __launch_bounds__(256) void outdot_kernel(
    const float* __restrict__ hf, const float* __restrict__ w2,
    const float* __restrict__ b2, float* __restrict__ out)
{
    int m = blockIdx.x * 8 + (threadIdx.x >> 5);
    int lane = threadIdx.x & 31;
    const float4* hp = (const float4*)(hf + (size_t)m * 256);
    const float4* wp = (const float4*)w2;
    float acc = 0.f;
    #pragma unroll
    for (int i = 0; i < 2; i++) {
        float4 h4 = hp[lane * 2 + i];
        float4 w4 = wp[lane * 2 + i];
        acc += h4.x * w4.x + h4.y * w4.y + h4.z * w4.z + h4.w * w4.w;
    }
    #pragma unroll
    for (int o = 16; o; o >>= 1) acc += __shfl_xor_sync(0xffffffffu, acc, o);
    if (lane == 0) out[m] = acc + b2[0];
}

// ---------------- launcher --------------------------------------------------
extern "C" void kernel_launch(void* const* d_in, const int* in_sizes, int n_in,
                              void* d_out, int out_size)
{
    const float* x      = (const float*)d_in[0];
    const int*   ei     = (const int*)  d_in[1];
    const float* in_w   = (const float*)d_in[3];
    const float* in_b   = (const float*)d_in[4];
    const float* msg_w1 = (const float*)d_in[5];
    const float* msg_b1 = (const float*)d_in[6];
    const float* msg_w2 = (const float*)d_in[7];
    const float* msg_b2 = (const float*)d_in[8];
    const float* upd_w1 = (const float*)d_in[9];
    const float* upd_b1 = (const float*)d_in[10];
    const float* upd_w2 = (const float*)d_in[11];
    const float* upd_b2 = (const float*)d_in[12];
    const float* bn_g   = (const float*)d_in[13];
    const float* bn_b   = (const float*)d_in[14];
    const float* bn_m   = (const float*)d_in[15];
    const float* bn_v   = (const float*)d_in[16];
    const float* mlp_w1 = (const float*)d_in[17];
    const float* mlp_b1 = (const float*)d_in[18];
    const float* mlp_w2 = (const float*)d_in[19];
    const float* mlp_b2 = (const float*)d_in[20];
    float* out = (float*)d_out;

    float *h0, *h1, *ba, *bb, *bc, *deginv, *gate, *bns, *bnt;
    int *cnt, *uix, *vix;
    __nv_bfloat16 *wth, *wtl;
    cudaGetSymbolAddress((void**)&h0, g_h0);
    cudaGetSymbolAddress((void**)&h1, g_h1);
    cudaGetSymbolAddress((void**)&bb, g_b);
    cudaGetSymbolAddress((void**)&bc, g_c);
    cudaGetSymbolAddress((void**)&ba, g_a);
    cudaGetSymbolAddress((void**)&cnt, g_cnt);
    cudaGetSymbolAddress((void**)&deginv, g_deginv);
    cudaGetSymbolAddress((void**)&gate, g_gate);
    cudaGetSymbolAddress((void**)&bns, g_bns);
    cudaGetSymbolAddress((void**)&bnt, g_bnt);
    cudaGetSymbolAddress((void**)&uix, g_uidx);
    cudaGetSymbolAddress((void**)&vix, g_vidx);
    cudaGetSymbolAddress((void**)&wth, g_wth);
    cudaGetSymbolAddress((void**)&wtl, g_wtl);

    cudaFuncSetAttribute(gemm_hmma, cudaFuncAttributeMaxDynamicSharedMemorySize, SMEM_BYTES);

    cudaMemsetAsync(cnt, 0, NN * sizeof(int), 0);
    count_kernel<<<NE / 256, 256>>>(ei, cnt);
    deg_kernel<<<NN / 256, 256>>>(cnt, deginv, gate);
    bnprep_kernel<<<NL, 256>>>(bn_g, bn_b, bn_m, bn_v, bns, bnt);
    idx_kernel<<<MF / 256, 256>>>(uix, vix);

    // weight prep (transpose + bf16 hi/lo split)
    wprep_kernel<<<dim3(256, NL), 256>>>(msg_w1,               131072, wth, wtl, WT_MSGD, 256);
    wprep_kernel<<<dim3(256, NL), 256>>>(msg_w1 + 256 * 256,   131072, wth, wtl, WT_MSGS, 256);
    wprep_kernel<<<dim3(256, NL), 256>>>(msg_w2,                65536, wth, wtl, WT_MSG2, 256);
    wprep_kernel<<<dim3(512, NL), 256>>>(upd_w1,               131072, wth, wtl, WT_UPD1, 512);
    wprep_kernel<<<dim3(256, NL), 256>>>(upd_w2,                65536, wth, wtl, WT_UPD2, 256);
    wprep_kernel<<<dim3(512, 1),  256>>>(mlp_w1,                    0, wth, wtl, WT_MLP1, 512);

    ingemm_kernel<<<NN / 32, 256>>>(x, in_w, in_b, h0);

    dim3 gN(2, NN / 128);   // 2 x 912
    for (int l = 0; l < NL; l++) {
        float* hc = (l & 1) ? h1 : h0;
        float* hn = (l & 1) ? h0 : h1;
        size_t lw = (size_t)l * WT_LSTRIDE;

        // a = h @ Wdst^T + msg_b1
        gemm_hmma<<<gN, 256, SMEM_BYTES>>>(hc, nullptr, nullptr, nullptr, nullptr,
            wth + lw + WT_MSGD, wtl + lw + WT_MSGD, 256,
            msg_b1 + l * 256, nullptr, nullptr, nullptr, nullptr, ba, 0);
        // b = h @ Wsrc^T
        gemm_hmma<<<gN, 256, SMEM_BYTES>>>(hc, nullptr, nullptr, nullptr, nullptr,
            wth + lw + WT_MSGS, wtl + lw + WT_MSGS, 256,
            nullptr, nullptr, nullptr, nullptr, nullptr, bb, 0);
        // aggH = scatter_add relu(a[dst] + b[src])
        cudaMemsetAsync(bc, 0, (size_t)NN * 256 * sizeof(float), 0);
        edge_kernel<<<NE / 8, 256>>>(ba, bb, ei, bc);
        // aggm = (aggH/deg) @ W2^T + gate*b2
        gemm_hmma<<<gN, 256, SMEM_BYTES>>>(bc, nullptr, nullptr, nullptr, deginv,
            wth + lw + WT_MSG2, wtl + lw + WT_MSG2, 256,
            msg_b2 + l * 256, gate, nullptr, nullptr, nullptr, bb, 0);
        // t = relu(h @ Utop^T + aggm @ Ubot^T + upd_b1)
        gemm_hmma<<<gN, 256, SMEM_BYTES>>>(hc, bb, nullptr, nullptr, nullptr,
            wth + lw + WT_UPD1, wtl + lw + WT_UPD1, 512,
            upd_b1 + l * 256, nullptr, nullptr, nullptr, nullptr, ba, 1);
        // h' = relu(BN(t @ U2^T + upd_b2)) + h
        gemm_hmma<<<gN, 256, SMEM_BYTES>>>(ba, nullptr, nullptr, nullptr, nullptr,
            wth + lw + WT_UPD2, wtl + lw + WT_UPD2, 256,
            upd_b2 + l * 256, nullptr, hc, bns + l * 256, bnt + l * 256, hn, 2);
    }

    float* hf = h1;  // after 5 layers
    // hidden_f = relu(h[u] @ Mtop^T + h[v] @ Mbot^T + mlp_b1)
    gemm_hmma<<<dim3(2, MF / 128), 256, SMEM_BYTES>>>(hf, hf, uix, vix, nullptr,
        wth + WT_MLP1, wtl + WT_MLP1, 512,
        mlp_b1, nullptr, nullptr, nullptr, nullptr, ba, 1);
    outdot_kernel<<<MF / 8, 256>>>(ba, mlp_w2, mlp_b2, out);
}